// round 5
// baseline (speedup 1.0000x reference)
#include <cuda_runtime.h>
#include <cuda_bf16.h>

// Problem constants
#define H      1501          // grid side (num_grid + 1)
#define PITCH  1536          // padded row pitch (floats) -> 128B-aligned rows
#define NUM_T  400           // sequential stencil steps
#define STEP_PARAM 0.225f    // diff * dt * num_grid^2 / x_len^2
#define DT     1e-7f

// Static device scratch (no allocations allowed).
// 2 ping-pong u buffers + 1 forcing buffer, padded: 3 * 1501*1536*4 B ~= 27.7 MB
__device__ float g_u0buf[H * PITCH];
__device__ float g_u1buf[H * PITCH];
__device__ float g_fbuf [H * PITCH];

// ---------------------------------------------------------------------------
// Init: copy u0 (edges intact!) into padded buffer, precompute forcing = dt*a.
// ---------------------------------------------------------------------------
__global__ void init_kernel(const float* __restrict__ u0,
                            const float* __restrict__ a)
{
    int x = blockIdx.x * blockDim.x + threadIdx.x;
    int y = blockIdx.y * blockDim.y + threadIdx.y;
    if (x >= H || y >= H) return;
    int src = y * H + x;
    int dst = y * PITCH + x;
    g_u0buf[dst] = u0[src];
    g_fbuf [dst] = DT * a[src];
    // pad columns are never read (interior stencil reads only x <= 1500)
}

// ---------------------------------------------------------------------------
// One diffusion step: u_out = mask * (u + 0.225*lap(u) + f)
// Edge outputs are exactly 0 (Dirichlet mask). Interior reads neighbors,
// which at step 1 include u0's original edge values (matches reference:
// the mask is applied to the *output* each step, not the input of step 1).
// ---------------------------------------------------------------------------
__global__ void __launch_bounds__(256)
step_kernel(const float* __restrict__ uin,
            const float* __restrict__ f,
            float* __restrict__ uout)
{
    int x = blockIdx.x * blockDim.x + threadIdx.x;
    int y = blockIdx.y * blockDim.y + threadIdx.y;
    if (x >= H || y >= H) return;
    int i = y * PITCH + x;

    float v = 0.0f;
    if (x > 0 && x < H - 1 && y > 0 && y < H - 1) {
        float c = uin[i];
        float lap = uin[i - 1] + uin[i + 1] + uin[i - PITCH] + uin[i + PITCH]
                  - 4.0f * c;
        v = fmaf(STEP_PARAM, lap, c) + f[i];
    }
    uout[i] = v;
}

// ---------------------------------------------------------------------------
// De-pad: copy padded result into contiguous d_out [H, H]
// ---------------------------------------------------------------------------
__global__ void copy_out_kernel(const float* __restrict__ ubuf,
                                float* __restrict__ out)
{
    int x = blockIdx.x * blockDim.x + threadIdx.x;
    int y = blockIdx.y * blockDim.y + threadIdx.y;
    if (x >= H || y >= H) return;
    out[y * H + x] = ubuf[y * PITCH + x];
}

extern "C" void kernel_launch(void* const* d_in, const int* in_sizes, int n_in,
                              void* d_out, int out_size)
{
    const float* u0 = (const float*)d_in[0];
    const float* a  = (const float*)d_in[1];
    float* out      = (float*)d_out;

    // Resolve device-global addresses every call (pure query, capture-safe,
    // no static guards -> identical host work on every invocation).
    float* p_u0 = nullptr;
    float* p_u1 = nullptr;
    float* p_f  = nullptr;
    cudaGetSymbolAddress((void**)&p_u0, g_u0buf);
    cudaGetSymbolAddress((void**)&p_u1, g_u1buf);
    cudaGetSymbolAddress((void**)&p_f,  g_fbuf);

    // Wide-x blocks: each warp spans 128 contiguous floats (512B), minimizing
    // distinct cache lines touched per warp and x-halo re-reads per block.
    dim3 block(128, 2);
    dim3 grid((H + block.x - 1) / block.x, (H + block.y - 1) / block.y);

    init_kernel<<<grid, block>>>(u0, a);

    float* bufs[2] = { p_u0, p_u1 };
    for (int t = 0; t < NUM_T; ++t) {
        float* uin  = bufs[t & 1];
        float* uout = bufs[(t + 1) & 1];
        step_kernel<<<grid, block>>>(uin, p_f, uout);
    }
    // After an even number of steps, result is back in bufs[0]
    copy_out_kernel<<<grid, block>>>(bufs[NUM_T & 1], out);
}

// round 9
// speedup vs baseline: 1.8310x; 1.8310x over previous
#include <cuda_runtime.h>
#include <cuda_bf16.h>

// Problem constants
#define H      1501          // grid side (num_grid + 1)
#define PITCH  1536          // padded row pitch (floats) -> 128B-aligned rows
#define NUM_T  400           // sequential stencil steps
#define SP     0.225f        // diff * dt * num_grid^2 / x_len^2
#define DT     1e-7f

// Static device scratch (no allocations allowed). Zero-initialized (.bss).
// 2 ping-pong u buffers + 1 forcing buffer, padded: 3 * 1501*1536*4 B ~= 27.7 MB
__device__ float g_u0buf[H * PITCH];
__device__ float g_u1buf[H * PITCH];
__device__ float g_fbuf [H * PITCH];

// ---------------------------------------------------------------------------
// Init: copy u0 (edges intact!) into padded buffer, precompute forcing = dt*a.
// ---------------------------------------------------------------------------
__global__ void init_kernel(const float* __restrict__ u0,
                            const float* __restrict__ a)
{
    int x = blockIdx.x * blockDim.x + threadIdx.x;
    int y = blockIdx.y * blockDim.y + threadIdx.y;
    if (x >= H || y >= H) return;
    int src = y * H + x;
    int dst = y * PITCH + x;
    g_u0buf[dst] = u0[src];
    g_fbuf [dst] = DT * a[src];
}

// ---------------------------------------------------------------------------
// One diffusion step, vectorized: each thread computes a 4(x) x 4(y) patch.
//   u_out = mask * (u + 0.225*lap(u) + f);   edges written exactly 0.
// float4 loads; x-neighbors from vector lanes + 2 scalar halo loads per row;
// y-reuse via rolling registers (rows y-1..y+4 loaded once for 4 output rows).
// ---------------------------------------------------------------------------
__global__ void __launch_bounds__(128)
step4_kernel(const float* __restrict__ uin,
             const float* __restrict__ f,
             float* __restrict__ uout)
{
    int tx = blockIdx.x * 32 + threadIdx.x;   // float4 column index
    int x0 = tx * 4;
    if (x0 > H - 1) return;                   // x0 in [0,1500]; pure-pad threads exit
    int y0 = (blockIdx.y * blockDim.y + threadIdx.y) * 4;
    if (y0 >= H) return;

    // Per-lane Dirichlet masks (x==0 or x>=1500 -> 0; covers pad lanes too)
    float m0 = (x0 == 0 || x0 >= H - 1) ? 0.0f : 1.0f;
    float m1 = (x0 + 1 >= H - 1) ? 0.0f : 1.0f;
    float m2 = (x0 + 2 >= H - 1) ? 0.0f : 1.0f;
    float m3 = (x0 + 3 >= H - 1) ? 0.0f : 1.0f;
    int xm = (x0 > 0) ? x0 - 1 : 0;           // clamped left-halo col (unused when x0==0)

    // Rolling center rows: rma = row(y-1), rc = row(y)
    int ymm = (y0 > 0) ? y0 - 1 : 0;
    float4 rma = *(const float4*)(uin + ymm * PITCH + x0);
    float4 rc  = *(const float4*)(uin + y0  * PITCH + x0);

    #pragma unroll
    for (int k = 0; k < 4; ++k) {
        int y = y0 + k;
        if (y < H) {
            int yp = (y + 1 < H) ? y + 1 : H - 1;
            float4 rpp = *(const float4*)(uin + yp * PITCH + x0);
            float4 outv;
            if (y == 0 || y == H - 1) {
                outv = make_float4(0.f, 0.f, 0.f, 0.f);
            } else {
                float  lm  = uin[y * PITCH + xm];       // left halo
                float  rt  = uin[y * PITCH + x0 + 4];   // right halo (<= x=1504, in-bounds)
                float4 fv  = *(const float4*)(f + y * PITCH + x0);
                outv.x = m0 * (fmaf(SP, lm   + rc.y + rma.x + rpp.x - 4.0f * rc.x, rc.x) + fv.x);
                outv.y = m1 * (fmaf(SP, rc.x + rc.z + rma.y + rpp.y - 4.0f * rc.y, rc.y) + fv.y);
                outv.z = m2 * (fmaf(SP, rc.y + rc.w + rma.z + rpp.z - 4.0f * rc.z, rc.z) + fv.z);
                outv.w = m3 * (fmaf(SP, rc.z + rt   + rma.w + rpp.w - 4.0f * rc.w, rc.w) + fv.w);
            }
            *(float4*)(uout + y * PITCH + x0) = outv;
            rma = rc;
            rc  = rpp;
        }
    }
}

// ---------------------------------------------------------------------------
// De-pad: copy padded result into contiguous d_out [H, H]
// ---------------------------------------------------------------------------
__global__ void copy_out_kernel(const float* __restrict__ ubuf,
                                float* __restrict__ out)
{
    int x = blockIdx.x * blockDim.x + threadIdx.x;
    int y = blockIdx.y * blockDim.y + threadIdx.y;
    if (x >= H || y >= H) return;
    out[y * H + x] = ubuf[y * PITCH + x];
}

extern "C" void kernel_launch(void* const* d_in, const int* in_sizes, int n_in,
                              void* d_out, int out_size)
{
    const float* u0 = (const float*)d_in[0];
    const float* a  = (const float*)d_in[1];
    float* out      = (float*)d_out;

    float* p_u0 = nullptr;
    float* p_u1 = nullptr;
    float* p_f  = nullptr;
    cudaGetSymbolAddress((void**)&p_u0, g_u0buf);
    cudaGetSymbolAddress((void**)&p_u1, g_u1buf);
    cudaGetSymbolAddress((void**)&p_f,  g_fbuf);

    {
        dim3 block(128, 2);
        dim3 grid((H + 127) / 128, (H + 1) / 2);
        init_kernel<<<grid, block>>>(u0, a);
    }

    // Step kernel: block 32x4 threads, each thread does 4x4 patch.
    // x: 376 float4 columns / 32 = 12 blocks; y: 1501 / 16 -> 94 blocks.
    dim3 sblock(32, 4);
    dim3 sgrid((((H + 3) / 4) + 31) / 32, (H + 15) / 16);   // 12 x 94 = 1128 blocks

    float* bufs[2] = { p_u0, p_u1 };
    for (int t = 0; t < NUM_T; ++t) {
        float* uin  = bufs[t & 1];
        float* uout = bufs[(t + 1) & 1];
        step4_kernel<<<sgrid, sblock>>>(uin, p_f, uout);
    }

    {
        dim3 block(128, 2);
        dim3 grid((H + 127) / 128, (H + 1) / 2);
        copy_out_kernel<<<grid, block>>>(bufs[NUM_T & 1], out);
    }
}